// round 1
// baseline (speedup 1.0000x reference)
#include <cuda_runtime.h>
#include <cstdint>

#define NEG_SLOPE 0.2f

static constexpr int Bb = 8;
static constexpr int Nn = 2048;
static constexpr int Dd = 128;

// Scratch (device globals; allocation-free rule)
__device__ float g_h[Bb * Nn * Dd];      // h, rounded to tf32 values stored as fp32
__device__ float g_ssrc[Bb * Nn];
__device__ float g_sdst[Bb * Nn];
__device__ float g_invd[Bb * Nn];

__device__ __forceinline__ uint32_t f2tf(float x) {
    uint32_t r;
    asm("cvt.rna.tf32.f32 %0, %1;" : "=r"(r) : "f"(x));
    return r;
}

__device__ __forceinline__ float lrelu(float v) { return v > 0.f ? v : NEG_SLOPE * v; }

__device__ __forceinline__ void mma8(float* d, const uint32_t* a, const uint32_t* b) {
    asm volatile(
        "mma.sync.aligned.m16n8k8.row.col.f32.tf32.tf32.f32 "
        "{%0,%1,%2,%3},{%4,%5,%6,%7},{%8,%9},{%0,%1,%2,%3};\n"
        : "+f"(d[0]), "+f"(d[1]), "+f"(d[2]), "+f"(d[3])
        : "r"(a[0]), "r"(a[1]), "r"(a[2]), "r"(a[3]), "r"(b[0]), "r"(b[1]));
}

__device__ __forceinline__ void cp16(void* s, const void* g) {
    uint32_t sa = (uint32_t)__cvta_generic_to_shared(s);
    asm volatile("cp.async.cg.shared.global [%0], [%1], 16;" :: "r"(sa), "l"(g));
}
__device__ __forceinline__ void cp_commit() { asm volatile("cp.async.commit_group;"); }
__device__ __forceinline__ void cp_wait0()  { asm volatile("cp.async.wait_group 0;"); }

// ---------------------------------------------------------------------------
// K1: h = x @ W  (M=16384, N=128, K=128), tf32 mma, store tf32-rounded h
// ---------------------------------------------------------------------------
__global__ __launch_bounds__(256) void k1_h(const float* __restrict__ x,
                                            const float* __restrict__ W) {
    __shared__ float As[64][36];
    __shared__ float Bs[32][136];
    int tid = threadIdx.x;
    int lane = tid & 31, w = tid >> 5;
    int wm = w >> 2, wn = w & 3;
    int g = lane >> 2, tg = lane & 3;
    long i0 = (long)blockIdx.x * 64;

    float acc[2][4][4];
#pragma unroll
    for (int mt = 0; mt < 2; mt++)
#pragma unroll
        for (int nt = 0; nt < 4; nt++)
#pragma unroll
            for (int q = 0; q < 4; q++) acc[mt][nt][q] = 0.f;

#pragma unroll
    for (int kc = 0; kc < 4; kc++) {
        int k0 = kc * 32;
        __syncthreads();
#pragma unroll
        for (int t = 0; t < 2; t++) {
            int e = tid + t * 256;
            int r = e >> 3, c4 = (e & 7) * 4;
            float4 xv = *(const float4*)(x + (i0 + r) * 128 + k0 + c4);
            uint4 o;
            o.x = f2tf(xv.x); o.y = f2tf(xv.y); o.z = f2tf(xv.z); o.w = f2tf(xv.w);
            *(uint4*)&As[r][c4] = o;
        }
#pragma unroll
        for (int t = 0; t < 4; t++) {
            int f = tid + t * 256;
            int r = f >> 5, c4 = (f & 31) * 4;
            float4 wv = *(const float4*)(W + (k0 + r) * 128 + c4);
            uint4 o;
            o.x = f2tf(wv.x); o.y = f2tf(wv.y); o.z = f2tf(wv.z); o.w = f2tf(wv.w);
            *(uint4*)&Bs[r][c4] = o;
        }
        __syncthreads();
#pragma unroll
        for (int ks = 0; ks < 4; ks++) {
            int ka = ks * 8;
            uint32_t af[2][4], bf[4][2];
#pragma unroll
            for (int mt = 0; mt < 2; mt++) {
                int rA = wm * 32 + mt * 16 + g;
                af[mt][0] = __float_as_uint(As[rA][ka + tg]);
                af[mt][1] = __float_as_uint(As[rA + 8][ka + tg]);
                af[mt][2] = __float_as_uint(As[rA][ka + tg + 4]);
                af[mt][3] = __float_as_uint(As[rA + 8][ka + tg + 4]);
            }
#pragma unroll
            for (int nt = 0; nt < 4; nt++) {
                int cB = wn * 32 + nt * 8 + g;
                bf[nt][0] = __float_as_uint(Bs[ka + tg][cB]);
                bf[nt][1] = __float_as_uint(Bs[ka + tg + 4][cB]);
            }
#pragma unroll
            for (int mt = 0; mt < 2; mt++)
#pragma unroll
                for (int nt = 0; nt < 4; nt++) mma8(acc[mt][nt], af[mt], bf[nt]);
        }
    }

    // store h rounded to tf32 (so downstream mma operands are valid tf32)
#pragma unroll
    for (int mt = 0; mt < 2; mt++)
#pragma unroll
        for (int nt = 0; nt < 4; nt++) {
            long r = i0 + wm * 32 + mt * 16 + g;
            int c = wn * 32 + nt * 8 + 2 * tg;
            float2 v0, v1;
            v0.x = __uint_as_float(f2tf(acc[mt][nt][0]));
            v0.y = __uint_as_float(f2tf(acc[mt][nt][1]));
            v1.x = __uint_as_float(f2tf(acc[mt][nt][2]));
            v1.y = __uint_as_float(f2tf(acc[mt][nt][3]));
            *(float2*)(g_h + r * 128 + c) = v0;
            *(float2*)(g_h + (r + 8) * 128 + c) = v1;
        }
}

// ---------------------------------------------------------------------------
// K2a: s_src[row] = h[row]·a[:128], s_dst[row] = h[row]·a[128:]
// ---------------------------------------------------------------------------
__global__ __launch_bounds__(256) void k2_s(const float* __restrict__ a) {
    __shared__ float as[256];
    int tid = threadIdx.x;
    as[tid] = a[tid];
    __syncthreads();
    int w = tid >> 5, lane = tid & 31;
    long row = (long)blockIdx.x * 8 + w;
    float4 h4 = *(const float4*)(g_h + row * 128 + lane * 4);
    int c = lane * 4;
    float s = h4.x * as[c] + h4.y * as[c + 1] + h4.z * as[c + 2] + h4.w * as[c + 3];
    float d = h4.x * as[128 + c] + h4.y * as[128 + c + 1] + h4.z * as[128 + c + 2] +
              h4.w * as[128 + c + 3];
#pragma unroll
    for (int o = 16; o; o >>= 1) {
        s += __shfl_xor_sync(0xFFFFFFFFu, s, o);
        d += __shfl_xor_sync(0xFFFFFFFFu, d, o);
    }
    if (lane == 0) {
        g_ssrc[row] = s;
        g_sdst[row] = d;
    }
}

// ---------------------------------------------------------------------------
// K2b: invd[i] = 1 / sum_j exp(lrelu(s_i + s_j))   (per batch)
// grid = 8 batches * 32 chunks of 64 rows; 4 j-segments per row (tid>>6)
// ---------------------------------------------------------------------------
__global__ __launch_bounds__(256) void k2_den() {
    __shared__ float sd[2048];
    __shared__ float part[256];
    int tid = threadIdx.x;
    int b = blockIdx.x >> 5, ic = blockIdx.x & 31;
    const float* sdg = g_sdst + b * 2048;
#pragma unroll
    for (int t = 0; t < 2; t++) {
        int f = tid + t * 256;
        *(float4*)&sd[f * 4] = *(const float4*)(sdg + f * 4);
    }
    int r = tid & 63, q = tid >> 6;
    float si = g_ssrc[b * 2048 + ic * 64 + r];
    __syncthreads();
    float acc = 0.f;
    int j0 = q * 512;
#pragma unroll 8
    for (int j = 0; j < 512; j++) {
        float e = si + sd[j0 + j];
        acc += __expf(lrelu(e));
    }
    part[tid] = acc;
    __syncthreads();
    if (tid < 64) {
        float den = part[tid] + part[tid + 64] + part[tid + 128] + part[tid + 192];
        g_invd[b * 2048 + ic * 64 + tid] = 1.f / den;
    }
}

// ---------------------------------------------------------------------------
// K3: out = lrelu( (adj + exp(lrelu(s_i+s_j)) * invd_i) @ h )
// block tile: 64 (i) x 128 (o), K=2048 (j) in chunks of 32, double-buffered.
// ---------------------------------------------------------------------------
struct SmemK3 {
    float A[2][64][36];     // coefficient tile (tf32 bit patterns)
    float Bt[2][32][136];   // h tile
    float sdst[2048];
    float ssrc[64];
    float invd[64];
};

__device__ __forceinline__ void coeff_tile(SmemK3& sm, int buf, int j0,
                                           const float4* v, int tid) {
#pragma unroll
    for (int t = 0; t < 2; t++) {
        int e = tid + t * 256;
        int r = e >> 3, c4 = (e & 7) * 4;
        float si = sm.ssrc[r];
        float id = sm.invd[r];
        uint4 o;
        o.x = f2tf(fmaf(__expf(lrelu(si + sm.sdst[j0 + c4 + 0])), id, v[t].x));
        o.y = f2tf(fmaf(__expf(lrelu(si + sm.sdst[j0 + c4 + 1])), id, v[t].y));
        o.z = f2tf(fmaf(__expf(lrelu(si + sm.sdst[j0 + c4 + 2])), id, v[t].z));
        o.w = f2tf(fmaf(__expf(lrelu(si + sm.sdst[j0 + c4 + 3])), id, v[t].w));
        *(uint4*)&sm.A[buf][r][c4] = o;
    }
}

__global__ __launch_bounds__(256) void k3_main(const float* __restrict__ adj,
                                               float* __restrict__ out) {
    extern __shared__ char smraw[];
    SmemK3& sm = *(SmemK3*)smraw;
    int tid = threadIdx.x, lane = tid & 31, w = tid >> 5;
    int wm = w >> 2, wn = w & 3, g = lane >> 2, tg = lane & 3;
    int b = blockIdx.y;
    int i0 = blockIdx.x * 64;
    const float* adjb = adj + ((long)b * 2048 + i0) * 2048;
    const float* hb = g_h + (long)b * 2048 * 128;

    // preload per-row vectors
#pragma unroll
    for (int t = 0; t < 2; t++) {
        int f = tid + t * 256;
        *(float4*)&sm.sdst[f * 4] = *(const float4*)(g_sdst + b * 2048 + f * 4);
    }
    if (tid < 64) {
        sm.ssrc[tid] = g_ssrc[b * 2048 + i0 + tid];
        sm.invd[tid] = g_invd[b * 2048 + i0 + tid];
    }

    float acc[2][4][4];
#pragma unroll
    for (int mt = 0; mt < 2; mt++)
#pragma unroll
        for (int nt = 0; nt < 4; nt++)
#pragma unroll
            for (int q = 0; q < 4; q++) acc[mt][nt][q] = 0.f;

    float4 v[2];

    // chunk 0 prologue
#pragma unroll
    for (int t = 0; t < 4; t++) {
        int f = tid + t * 256;
        int r = f >> 5, c4 = (f & 31) * 4;
        cp16(&sm.Bt[0][r][c4], hb + (long)r * 128 + c4);
    }
    cp_commit();
#pragma unroll
    for (int t = 0; t < 2; t++) {
        int e = tid + t * 256;
        int r = e >> 3, c4 = (e & 7) * 4;
        v[t] = __ldcs((const float4*)(adjb + (long)r * 2048 + c4));
    }
    __syncthreads();   // sdst/ssrc/invd visible
    cp_wait0();
    coeff_tile(sm, 0, 0, v, tid);
    __syncthreads();

    for (int c = 0; c < 64; c++) {
        int buf = c & 1;
        int j1 = (c + 1) * 32;
        if (c < 63) {
#pragma unroll
            for (int t = 0; t < 2; t++) {
                int e = tid + t * 256;
                int r = e >> 3, c4 = (e & 7) * 4;
                v[t] = __ldcs((const float4*)(adjb + (long)r * 2048 + j1 + c4));
            }
#pragma unroll
            for (int t = 0; t < 4; t++) {
                int f = tid + t * 256;
                int r = f >> 5, c4 = (f & 31) * 4;
                cp16(&sm.Bt[buf ^ 1][r][c4], hb + (long)(j1 + r) * 128 + c4);
            }
            cp_commit();
        }
        // MMA on current buffers
#pragma unroll
        for (int ks = 0; ks < 4; ks++) {
            int ka = ks * 8;
            uint32_t af[2][4], bf[4][2];
#pragma unroll
            for (int mt = 0; mt < 2; mt++) {
                int rA = wm * 32 + mt * 16 + g;
                af[mt][0] = __float_as_uint(sm.A[buf][rA][ka + tg]);
                af[mt][1] = __float_as_uint(sm.A[buf][rA + 8][ka + tg]);
                af[mt][2] = __float_as_uint(sm.A[buf][rA][ka + tg + 4]);
                af[mt][3] = __float_as_uint(sm.A[buf][rA + 8][ka + tg + 4]);
            }
#pragma unroll
            for (int nt = 0; nt < 4; nt++) {
                int cB = wn * 32 + nt * 8 + g;
                bf[nt][0] = __float_as_uint(sm.Bt[buf][ka + tg][cB]);
                bf[nt][1] = __float_as_uint(sm.Bt[buf][ka + tg + 4][cB]);
            }
#pragma unroll
            for (int mt = 0; mt < 2; mt++)
#pragma unroll
                for (int nt = 0; nt < 4; nt++) mma8(acc[mt][nt], af[mt], bf[nt]);
        }
        if (c < 63) {
            cp_wait0();
            coeff_tile(sm, buf ^ 1, j1, v, tid);
        }
        __syncthreads();
    }

    // epilogue: final leaky_relu, write out
    float* ob = out + ((long)b * 2048 + i0) * 128;
#pragma unroll
    for (int mt = 0; mt < 2; mt++)
#pragma unroll
        for (int nt = 0; nt < 4; nt++) {
            int r = wm * 32 + mt * 16 + g;
            int cc = wn * 32 + nt * 8 + 2 * tg;
            float2 v0, v1;
            v0.x = lrelu(acc[mt][nt][0]);
            v0.y = lrelu(acc[mt][nt][1]);
            v1.x = lrelu(acc[mt][nt][2]);
            v1.y = lrelu(acc[mt][nt][3]);
            *(float2*)(ob + (long)r * 128 + cc) = v0;
            *(float2*)(ob + (long)(r + 8) * 128 + cc) = v1;
        }
}

// ---------------------------------------------------------------------------
extern "C" void kernel_launch(void* const* d_in, const int* in_sizes, int n_in,
                              void* d_out, int out_size) {
    (void)in_sizes; (void)n_in; (void)out_size;
    const float* x   = (const float*)d_in[0];
    const float* adj = (const float*)d_in[1];
    const float* W   = (const float*)d_in[2];
    const float* a   = (const float*)d_in[3];
    float* out = (float*)d_out;

    k1_h<<<256, 256>>>(x, W);
    k2_s<<<2048, 256>>>(a);
    k2_den<<<256, 256>>>();
    cudaFuncSetAttribute(k3_main, cudaFuncAttributeMaxDynamicSharedMemorySize,
                         (int)sizeof(SmemK3));
    k3_main<<<dim3(32, 8), 256, sizeof(SmemK3)>>>(adj, out);
}